// round 10
// baseline (speedup 1.0000x reference)
#include <cuda_runtime.h>
#include <cstdint>

#define NCL     16         // clusters
#define CSZ     8          // CTAs per cluster
#define NBLK    (NCL*CSZ)  // 128 CTAs
#define NTHR    256
#define BPC     16         // batch cols per cluster
#define HD      256
#define DIM     3
#define LT      20
#define NCLASS  10
#define NSTEPS  380
#define ROWS    32
#define MATW    8320       // words per packed matrix: 65 k4 x 32 rows x 4

// ---- smem word offsets ----
#define OFF_W    0                   // [4][65][32][4] = 33280
#define OFF_B    33280               // [4][32]
#define OFF_T    33408               // [20]
#define OFF_MB   33428               // 4 mbarriers (u64) = 8 words (byte 8-aligned)
#define OFF_SZ   33436               // STG_Z  [8 k4][16 c][4] = 512
#define OFF_SH0  33948               // STG_H0 512
#define OFF_SH1  34460               // STG_H1 512
#define OFF_ASM  34972               // assembled acts [64 k4][16 c][4] = 4096
#define SMEM_WORDS 39068
#define SMEM_BYTES (SMEM_WORDS*4)    // 156272 B

// barrier ids: 0 = H0 ready (L1 out / L3 out uses 2), 1 = H1 ready, 2 = H0' ready, 3 = Z ready
// ---------------- helpers ----------------
__device__ __forceinline__ float2 ffma2(float2 a, float2 b, float2 c) {
    float2 d;
    asm("fma.rn.f32x2 %0, %1, %2, %3;"
        : "=l"(*(unsigned long long*)&d)
        : "l"(*(unsigned long long*)&a),
          "l"(*(unsigned long long*)&b),
          "l"(*(unsigned long long*)&c));
    return d;
}
__device__ __forceinline__ float lipswish(float x) {
    return 0.909f * x / (1.0f + __expf(-x));
}
__device__ __forceinline__ uint32_t smem_u32(const void* p) {
    uint32_t a;
    asm("{ .reg .u64 t; cvta.to.shared.u64 t, %1; cvt.u32.u64 %0, t; }" : "=r"(a) : "l"(p));
    return a;
}
__device__ __forceinline__ uint32_t mapa_u32(uint32_t a, uint32_t rank) {
    uint32_t d;
    asm("mapa.shared::cluster.u32 %0, %1, %2;" : "=r"(d) : "r"(a), "r"(rank));
    return d;
}
__device__ __forceinline__ void cluster_bar() {
    asm volatile("barrier.cluster.arrive.aligned;" ::: "memory");
    asm volatile("barrier.cluster.wait.aligned;"   ::: "memory");
}
__device__ __forceinline__ void mb_init(uint32_t mb, uint32_t cnt) {
    asm volatile("mbarrier.init.shared.b64 [%0], %1;" :: "r"(mb), "r"(cnt) : "memory");
}
// wait with cluster-scope acquire (peer smem reads follow)
__device__ __forceinline__ void mb_wait(uint32_t mb, uint32_t parity) {
    uint32_t done;
    asm volatile(
        "{\n\t.reg .pred p;\n\t"
        "mbarrier.try_wait.parity.acquire.cluster.shared::cta.b64 p, [%1], %2, 0x989680;\n\t"
        "selp.b32 %0, 1, 0, p;\n\t}"
        : "=r"(done) : "r"(mb), "r"(parity) : "memory");
    while (!done) {
        asm volatile(
            "{\n\t.reg .pred p;\n\t"
            "mbarrier.try_wait.parity.acquire.cluster.shared::cta.b64 p, [%1], %2, 0x989680;\n\t"
            "selp.b32 %0, 1, 0, p;\n\t}"
            : "=r"(done) : "r"(mb), "r"(parity) : "memory");
    }
}
// elected thread: arrive on barrier `bi` of every CTA in the cluster (release)
__device__ __forceinline__ void arrive_all(const uint32_t* __restrict__ pb, int bi) {
    uint32_t moff = (uint32_t)(OFF_MB + bi * 2) * 4u;
#pragma unroll
    for (int rr = 0; rr < CSZ; rr++) {
        asm volatile("mbarrier.arrive.release.cluster.shared::cluster.b64 _, [%0];"
                     :: "r"(pb[rr] + moff) : "memory");
    }
}
// pull all 8 CTAs' 2KB staging (word off stg) into local assembled buffer (16KB)
__device__ __forceinline__ void pull(const uint32_t* __restrict__ pb, int stg,
                                     float* __restrict__ dst, int tid) {
#pragma unroll
    for (int i4 = 0; i4 < 4; i4++) {
        int i = i4 * 256 + tid;          // float4 index 0..1023 (= k4*16 + c)
        int p = i >> 7;                  // source CTA (k4>>3)
        uint32_t src = pb[p] + (uint32_t)(stg + (i & 127) * 4) * 4u;
        float4 v;
        asm volatile("ld.shared::cluster.v4.f32 {%0,%1,%2,%3}, [%4];"
                     : "=f"(v.x), "=f"(v.y), "=f"(v.z), "=f"(v.w) : "r"(src));
        *(float4*)(dst + i * 4) = v;
    }
}
// dot over 64 k4: interleaved weights [k4][32r][4] vs assembled acts [k4][16c][4]
__device__ __forceinline__ float dot_i(const float4* __restrict__ w4,
                                       const float4* __restrict__ a4,
                                       int r, int cI) {
    float2 s0 = {0,0}, s1 = {0,0};
#pragma unroll 8
    for (int k = 0; k < 64; k++) {
        float4 wv = w4[(k << 5) + r];
        float4 av = a4[(k << 4) + cI];
        s0 = ffma2(make_float2(wv.x, wv.y), make_float2(av.x, av.y), s0);
        s1 = ffma2(make_float2(wv.z, wv.w), make_float2(av.z, av.w), s1);
    }
    return (s0.x + s0.y) + (s1.x + s1.y);
}

// ---------------- kernel ----------------
__global__ void __launch_bounds__(NTHR, 1)
ncde_kernel(const float* __restrict__ coeffs, const float* __restrict__ times_g,
            const float* __restrict__ W_init, const float* __restrict__ b_init,
            const float* __restrict__ W_in,   const float* __restrict__ b_in,
            const float* __restrict__ W_hh,   const float* __restrict__ b_hh,
            const float* __restrict__ W_out,  const float* __restrict__ b_out,
            const float* __restrict__ Wc1,    const float* __restrict__ bc1,
            const float* __restrict__ Wc2,    const float* __restrict__ bc2,
            float* __restrict__ out) {
    extern __shared__ float sm[];
    const int tid = threadIdx.x;
    const int cl  = blockIdx.x / CSZ;
    unsigned rank;
    asm("mov.u32 %0, %%cluster_ctarank;" : "=r"(rank));
    const int r  = tid >> 3;             // 0..31 local row
    const int cA = tid & 7;              // cols cA and cA+8
    const int cB = cA + 8;
    const int R  = (int)rank * ROWS + r; // global row
    const int sA = (r >> 2) * 64 + cA * 4 + (r & 3);  // staging slot (r, cA)
    const int sB = (r >> 2) * 64 + cB * 4 + (r & 3);
    const bool lead = (tid == 0);

    const uint32_t smb = smem_u32(sm);
    uint32_t pb[CSZ];
#pragma unroll
    for (int rr = 0; rr < CSZ; rr++) pb[rr] = mapa_u32(smb, rr);
#define MBA(i) (smb + (OFF_MB + (i)*2)*4)

    // ---- repack weights into [k4][32r][4] interleave (zero-padded), biases, times ----
    {
        const float* srcs[4] = {W_in, W_hh, W_hh + HD*HD, W_out};
        const int    kw[4]   = {HD + DIM, HD, HD, HD};
#pragma unroll
        for (int m = 0; m < 4; m++) {
            const float* s = srcs[m];
            const int K = kw[m];
            float* wd = sm + OFF_W + m*MATW;
            for (int idx = tid; idx < ROWS*260; idx += NTHR) {
                int row = idx / 260, k = idx % 260;
                float v = (k < K) ? s[((int)rank*ROWS + row)*K + k] : 0.0f;
                wd[(k >> 2)*128 + row*4 + (k & 3)] = v;
            }
        }
        const float* bs[4] = {b_in, b_hh, b_hh + HD, b_out};
        if (tid < ROWS)
#pragma unroll
            for (int m = 0; m < 4; m++)
                sm[OFF_B + m*ROWS + tid] = bs[m][(int)rank*ROWS + tid];
        if (tid < LT) sm[OFF_T + tid] = times_g[tid];
    }
    if (tid == 0) {
#pragma unroll
        for (int i = 0; i < 4; i++) mb_init(MBA(i), CSZ);   // 8 arrivals per phase
    }
    __syncthreads();
    cluster_bar();     // all barriers live before any arrive

    const float t0 = sm[OFF_T];
    const float dt = (sm[OFF_T + LT - 1] - t0) / (float)NSTEPS;
    float t = t0;

    auto eval_x = [&](int col, float tt) -> float3 {
        int idx = 0;
#pragma unroll
        for (int i = 1; i <= LT - 2; i++) idx = (sm[OFF_T + i] <= tt) ? i : idx;
        float ta = sm[OFF_T + idx], tb = sm[OFF_T + idx + 1];
        float w = (tt - ta) / (tb - ta), om = 1.0f - w;
        const float* c0 = coeffs + ((cl*BPC + col)*LT + idx)*DIM;
        float3 x;
        x.x = c0[0]*om + c0[DIM+0]*w;
        x.y = c0[1]*om + c0[DIM+1]*w;
        x.z = c0[2]*om + c0[DIM+2]*w;
        return x;
    };

    // ---- z0 for MY rows only -> STG_Z, then announce via barrier 3 (completion #0) ----
    {
        float3 xa = eval_x(cA, t);
        float3 xb = eval_x(cB, t);
        const float wa = W_init[R*DIM+0], wb = W_init[R*DIM+1], wc = W_init[R*DIM+2];
        const float bb = b_init[R];
        sm[OFF_SZ + sA] = bb + wa*xa.x + wb*xa.y + wc*xa.z;
        sm[OFF_SZ + sB] = bb + wa*xb.x + wb*xb.y + wc*xb.z;
    }
    __syncthreads();
    if (lead) arrive_all(pb, 3);

    const float4* w0 = (const float4*)(sm + OFF_W + 0*MATW);
    const float4* w1 = (const float4*)(sm + OFF_W + 1*MATW);
    const float4* w2 = (const float4*)(sm + OFF_W + 2*MATW);
    const float4* w3 = (const float4*)(sm + OFF_W + 3*MATW);
    const float4* aA = (const float4*)(sm + OFF_ASM);
    const float bi0 = sm[OFF_B + 0*ROWS + r];
    const float bi1 = sm[OFF_B + 1*ROWS + r];
    const float bi2 = sm[OFF_B + 2*ROWS + r];
    const float bi3 = sm[OFF_B + 3*ROWS + r];
    const float wt0 = sm[OFF_W + 64*128 + r*4 + 0];   // W_in x-tail (k=256..258)
    const float wt1 = sm[OFF_W + 64*128 + r*4 + 1];
    const float wt2 = sm[OFF_W + 64*128 + r*4 + 2];

    // ---- main Euler loop: 4 pull-phases per step ----
    for (int s = 0; s < NSTEPS; s++) {
        const uint32_t ph = (uint32_t)(s & 1);

        // L1: z -> h0
        mb_wait(MBA(3), ph);
        pull(pb, OFF_SZ, sm + OFF_ASM, tid);
        __syncthreads();
        {
            float3 xa = eval_x(cA, t);
            float3 xb = eval_x(cB, t);
            float vA = lipswish(dot_i(w0, aA, r, cA) + wt0*xa.x + wt1*xa.y + wt2*xa.z + bi0);
            float vB = lipswish(dot_i(w0, aA, r, cB) + wt0*xb.x + wt1*xb.y + wt2*xb.z + bi0);
            sm[OFF_SH0 + sA] = vA;
            sm[OFF_SH0 + sB] = vB;
        }
        __syncthreads();
        if (lead) arrive_all(pb, 0);

        // L2: h0 -> h1
        mb_wait(MBA(0), ph);
        pull(pb, OFF_SH0, sm + OFF_ASM, tid);
        __syncthreads();
        sm[OFF_SH1 + sA] = lipswish(dot_i(w1, aA, r, cA) + bi1);
        sm[OFF_SH1 + sB] = lipswish(dot_i(w1, aA, r, cB) + bi1);
        __syncthreads();
        if (lead) arrive_all(pb, 1);

        // L3: h1 -> h0' (STG_H0 overwrite safe: all peers pulled it before arriving bar 0? 
        //  -> they pulled during L2, before arriving bar 1; we passed bar-1 wait)
        mb_wait(MBA(1), ph);
        pull(pb, OFF_SH1, sm + OFF_ASM, tid);
        __syncthreads();
        sm[OFF_SH0 + sA] = lipswish(dot_i(w2, aA, r, cA) + bi2);
        sm[OFF_SH0 + sB] = lipswish(dot_i(w2, aA, r, cB) + bi2);
        __syncthreads();
        if (lead) arrive_all(pb, 2);

        // L4: h0' -> z update (STG_Z overwrite safe: peers pulled Z during L1)
        mb_wait(MBA(2), ph);
        pull(pb, OFF_SH0, sm + OFF_ASM, tid);
        __syncthreads();
        {
            float fA = tanhf(dot_i(w3, aA, r, cA) + bi3);
            float fB = tanhf(dot_i(w3, aA, r, cB) + bi3);
            sm[OFF_SZ + sA] = fmaf(dt, fA, sm[OFF_SZ + sA]);
            sm[OFF_SZ + sB] = fmaf(dt, fB, sm[OFF_SZ + sB]);
        }
        __syncthreads();
        if (lead) arrive_all(pb, 3);

        t = t + dt;
    }

    // ---- epilogue: bar3 completion #380 -> parity 0 ----
    mb_wait(MBA(3), 0u);
    pull(pb, OFF_SZ, sm + OFF_ASM, tid);
    __syncthreads();
    {
        const float4* wg = (const float4*)(Wc1 + R*HD);
        const float bi4 = __ldg(bc1 + R);
        float oA, oB;
#pragma unroll
        for (int gg = 0; gg < 2; gg++) {
            int c = gg ? cB : cA;
            float2 s0 = {0,0}, s1 = {0,0};
#pragma unroll 8
            for (int k = 0; k < 64; k++) {
                float4 wv = __ldg(wg + k);
                float4 av = aA[(k << 4) + c];
                s0 = ffma2(make_float2(wv.x, wv.y), make_float2(av.x, av.y), s0);
                s1 = ffma2(make_float2(wv.z, wv.w), make_float2(av.z, av.w), s1);
            }
            float v = fmaxf((s0.x + s0.y) + (s1.x + s1.y) + bi4, 0.0f);
            if (gg) oB = v; else oA = v;
        }
        sm[OFF_SH0 + sA] = oA;
        sm[OFF_SH0 + sB] = oB;
    }
    __syncthreads();
    if (lead) arrive_all(pb, 0);
    mb_wait(MBA(0), 0u);                    // completion #380 of bar0
    pull(pb, OFF_SH0, sm + OFF_ASM, tid);
    __syncthreads();

    // ---- out = Wc2 @ h + bc2 (rank 0; 160 items) ----
    if (rank == 0 && tid < BPC*NCLASS) {
        int b = tid / NCLASS, cls = tid % NCLASS;
        const float4* wr = (const float4*)(Wc2 + cls*HD);
        float2 s0 = {0,0}, s1 = {0,0};
#pragma unroll 8
        for (int k = 0; k < 64; k++) {
            float4 w = __ldg(wr + k);
            float4 h = aA[(k << 4) + b];
            s0 = ffma2(make_float2(w.x, w.y), make_float2(h.x, h.y), s0);
            s1 = ffma2(make_float2(w.z, w.w), make_float2(h.z, h.w), s1);
        }
        out[(cl*BPC + b)*NCLASS + cls] = __ldg(bc2 + cls) + (s0.x + s0.y) + (s1.x + s1.y);
    }

    cluster_bar();   // keep smem alive while peers may still pull
}

// ---------------- launch ----------------
extern "C" void kernel_launch(void* const* d_in, const int* in_sizes, int n_in,
                              void* d_out, int out_size) {
    (void)in_sizes; (void)n_in; (void)out_size;
    cudaFuncSetAttribute(ncde_kernel, cudaFuncAttributeMaxDynamicSharedMemorySize, SMEM_BYTES);

    cudaLaunchConfig_t cfg = {};
    cfg.gridDim  = dim3(NBLK, 1, 1);
    cfg.blockDim = dim3(NTHR, 1, 1);
    cfg.dynamicSmemBytes = SMEM_BYTES;
    cfg.stream = 0;

    cudaLaunchAttribute attrs[1];
    attrs[0].id = cudaLaunchAttributeClusterDimension;
    attrs[0].val.clusterDim.x = CSZ;
    attrs[0].val.clusterDim.y = 1;
    attrs[0].val.clusterDim.z = 1;
    cfg.attrs = attrs;
    cfg.numAttrs = 1;

    cudaLaunchKernelEx(&cfg, ncde_kernel,
        (const float*)d_in[0],  (const float*)d_in[1],
        (const float*)d_in[2],  (const float*)d_in[3],
        (const float*)d_in[4],  (const float*)d_in[5],
        (const float*)d_in[6],  (const float*)d_in[7],
        (const float*)d_in[8],  (const float*)d_in[9],
        (const float*)d_in[10], (const float*)d_in[11],
        (const float*)d_in[12], (const float*)d_in[13],
        (float*)d_out);
}

// round 13
// speedup vs baseline: 1.6645x; 1.6645x over previous
#include <cuda_runtime.h>
#include <cstdint>

#define NCL     16         // clusters
#define CSZ     8          // CTAs per cluster
#define NBLK    (NCL*CSZ)  // 128 CTAs
#define NTHR    256
#define BPC     16         // batch cols per cluster
#define HD      256
#define DIM     3
#define LT      20
#define NCLASS  10
#define NSTEPS  380
#define ROWS    32
#define MATW    8320       // words per packed matrix: 65 k4 x 32 rows x 4

// ---- smem word offsets ----
#define OFF_W   0                    // [4][65][32][4] = 33280
#define OFF_B   33280                // [4][32]
#define OFF_T   33408                // [20]
#define OFF_MB  33428                // 4 mbarriers (u64) = 8 words (byte 8-aligned)
#define OFF_Z   33436                // [65 k4][16 cols][4] (block 64 = x at init)
#define OFF_H0  (OFF_Z + 65*64)      // [64][16][4]
#define OFF_H1  (OFF_H0 + 64*64)
#define SMEM_WORDS (OFF_H1 + 64*64)  // 45788
#define SMEM_BYTES (SMEM_WORDS*4)    // 183152 B

// barriers: 0=H0 ready(L1), 1=H1 ready(L2), 2=H0' ready(L3), 3=Z ready(L4)
#define TXB 16384u                   // 8 CTAs * 512 values * 4B per phase

// ---------------- helpers ----------------
__device__ __forceinline__ float2 ffma2(float2 a, float2 b, float2 c) {
    float2 d;
    asm("fma.rn.f32x2 %0, %1, %2, %3;"
        : "=l"(*(unsigned long long*)&d)
        : "l"(*(unsigned long long*)&a),
          "l"(*(unsigned long long*)&b),
          "l"(*(unsigned long long*)&c));
    return d;
}
__device__ __forceinline__ float lipswish(float x) {
    return 0.909f * x / (1.0f + __expf(-x));
}
__device__ __forceinline__ uint32_t smem_u32(const void* p) {
    uint32_t a;
    asm("{ .reg .u64 t; cvta.to.shared.u64 t, %1; cvt.u32.u64 %0, t; }" : "=r"(a) : "l"(p));
    return a;
}
__device__ __forceinline__ uint32_t mapa_u32(uint32_t a, uint32_t rank) {
    uint32_t d;
    asm("mapa.shared::cluster.u32 %0, %1, %2;" : "=r"(d) : "r"(a), "r"(rank));
    return d;
}
__device__ __forceinline__ void cluster_bar() {
    asm volatile("barrier.cluster.arrive.aligned;" ::: "memory");
    asm volatile("barrier.cluster.wait.aligned;"   ::: "memory");
}
__device__ __forceinline__ void mb_init(uint32_t mb, uint32_t cnt) {
    asm volatile("mbarrier.init.shared.b64 [%0], %1;" :: "r"(mb), "r"(cnt) : "memory");
}
__device__ __forceinline__ void mb_arm(uint32_t mb, uint32_t tx) {
    asm volatile("mbarrier.arrive.expect_tx.shared.b64 _, [%0], %1;" :: "r"(mb), "r"(tx) : "memory");
}
__device__ __forceinline__ void mb_wait(uint32_t mb, uint32_t parity) {
    uint32_t done;
    asm volatile(
        "{\n\t.reg .pred p;\n\t"
        "mbarrier.try_wait.parity.acquire.cta.shared::cta.b64 p, [%1], %2, 0x989680;\n\t"
        "selp.b32 %0, 1, 0, p;\n\t}"
        : "=r"(done) : "r"(mb), "r"(parity) : "memory");
    while (!done) {
        asm volatile(
            "{\n\t.reg .pred p;\n\t"
            "mbarrier.try_wait.parity.acquire.cta.shared::cta.b64 p, [%1], %2, 0x989680;\n\t"
            "selp.b32 %0, 1, 0, p;\n\t}"
            : "=r"(done) : "r"(mb), "r"(parity) : "memory");
    }
}
// send one value to the same slot in all 8 CTAs' smem, feeding barrier bi
__device__ __forceinline__ void scatter(const uint32_t* __restrict__ pb,
                                        int bi, uint32_t word_off, float v) {
    uint32_t eoff = word_off * 4u;
    uint32_t moff = (uint32_t)(OFF_MB + bi * 2) * 4u;
#pragma unroll
    for (int rr = 0; rr < CSZ; rr++) {
        asm volatile(
            "st.async.weak.shared::cluster.mbarrier::complete_tx::bytes.b32 [%0], %1, [%2];"
            :: "r"(pb[rr] + eoff), "f"(v), "r"(pb[rr] + moff) : "memory");
    }
}
// dual-column dot over 64 k4: one weight load serves both columns
__device__ __forceinline__ float2 dot_i2(const float4* __restrict__ w4,
                                         const float4* __restrict__ a4,
                                         int r, int cA) {
    float2 sa0 = {0,0}, sa1 = {0,0}, sb0 = {0,0}, sb1 = {0,0};
#pragma unroll 8
    for (int k = 0; k < 64; k++) {
        float4 wv = w4[(k << 5) + r];
        float4 aa = a4[(k << 4) + cA];
        float4 ab = a4[(k << 4) + cA + 8];
        float2 wlo = make_float2(wv.x, wv.y), whi = make_float2(wv.z, wv.w);
        sa0 = ffma2(wlo, make_float2(aa.x, aa.y), sa0);
        sa1 = ffma2(whi, make_float2(aa.z, aa.w), sa1);
        sb0 = ffma2(wlo, make_float2(ab.x, ab.y), sb0);
        sb1 = ffma2(whi, make_float2(ab.z, ab.w), sb1);
    }
    return make_float2((sa0.x + sa0.y) + (sa1.x + sa1.y),
                       (sb0.x + sb0.y) + (sb1.x + sb1.y));
}

// ---------------- kernel ----------------
__global__ void __launch_bounds__(NTHR, 1)
ncde_kernel(const float* __restrict__ coeffs, const float* __restrict__ times_g,
            const float* __restrict__ W_init, const float* __restrict__ b_init,
            const float* __restrict__ W_in,   const float* __restrict__ b_in,
            const float* __restrict__ W_hh,   const float* __restrict__ b_hh,
            const float* __restrict__ W_out,  const float* __restrict__ b_out,
            const float* __restrict__ Wc1,    const float* __restrict__ bc1,
            const float* __restrict__ Wc2,    const float* __restrict__ bc2,
            float* __restrict__ out) {
    extern __shared__ float sm[];
    const int tid = threadIdx.x;
    const int cl  = blockIdx.x / CSZ;
    unsigned rank;
    asm("mov.u32 %0, %%cluster_ctarank;" : "=r"(rank));
    const int r  = tid >> 3;             // 0..31 local row
    const int cA = tid & 7;              // cols cA and cA+8
    const int cB = cA + 8;
    const int R  = (int)rank * ROWS + r; // global row
    const uint32_t zw = (uint32_t)(((R >> 2) << 6) + (R & 3));  // interleave base for row R
    const bool lead = (tid == 0);

    const uint32_t smb = smem_u32(sm);
    uint32_t pb[CSZ];
#pragma unroll
    for (int rr = 0; rr < CSZ; rr++) pb[rr] = mapa_u32(smb, rr);
#define MBA(i) (smb + (OFF_MB + (i)*2)*4)

    // ---- repack weights into [k4][32r][4] interleave (zero-padded), biases, times ----
    {
        const float* srcs[4] = {W_in, W_hh, W_hh + HD*HD, W_out};
        const int    kw[4]   = {HD + DIM, HD, HD, HD};
#pragma unroll
        for (int m = 0; m < 4; m++) {
            const float* s = srcs[m];
            const int K = kw[m];
            float* wd = sm + OFF_W + m*MATW;
            for (int idx = tid; idx < ROWS*260; idx += NTHR) {
                int row = idx / 260, k = idx % 260;
                float v = (k < K) ? s[((int)rank*ROWS + row)*K + k] : 0.0f;
                wd[(k >> 2)*128 + row*4 + (k & 3)] = v;
            }
        }
        const float* bs[4] = {b_in, b_hh, b_hh + HD, b_out};
        if (tid < ROWS)
#pragma unroll
            for (int m = 0; m < 4; m++)
                sm[OFF_B + m*ROWS + tid] = bs[m][(int)rank*ROWS + tid];
        if (tid < LT) sm[OFF_T + tid] = times_g[tid];
    }
    if (tid == 0) {
#pragma unroll
        for (int i = 0; i < 4; i++) { mb_init(MBA(i), 1); mb_arm(MBA(i), TXB); }
    }
    __syncthreads();
    cluster_bar();     // all barriers live before any st.async

    const float t0 = sm[OFF_T];
    const float dt = (sm[OFF_T + LT - 1] - t0) / (float)NSTEPS;
    float t = t0;

    auto eval_x = [&](int col, float tt) -> float3 {
        int idx = 0;
#pragma unroll
        for (int i = 1; i <= LT - 2; i++) idx = (sm[OFF_T + i] <= tt) ? i : idx;
        float ta = sm[OFF_T + idx], tb = sm[OFF_T + idx + 1];
        float w = (tt - ta) / (tb - ta), om = 1.0f - w;
        const float* c0 = coeffs + ((cl*BPC + col)*LT + idx)*DIM;
        float3 x;
        x.x = c0[0]*om + c0[DIM+0]*w;
        x.y = c0[1]*om + c0[DIM+1]*w;
        x.z = c0[2]*om + c0[DIM+2]*w;
        return x;
    };

    // ---- z0 = W_init @ x(t0) + b_init, replicated locally (x staged in Z block 64) ----
    if (tid < BPC) {
        float3 x = eval_x(tid, t);
        sm[OFF_Z + 64*64 + tid*4 + 0] = x.x;
        sm[OFF_Z + 64*64 + tid*4 + 1] = x.y;
        sm[OFF_Z + 64*64 + tid*4 + 2] = x.z;
    }
    __syncthreads();
    for (int i = 0; i < (HD*BPC)/NTHR; i++) {
        int idx = i*NTHR + tid;
        int col = idx & 15, row = idx >> 4;
        const float* xv = sm + OFF_Z + 64*64 + col*4;
        float v = b_init[row]
                + W_init[row*DIM+0]*xv[0]
                + W_init[row*DIM+1]*xv[1]
                + W_init[row*DIM+2]*xv[2];
        sm[OFF_Z + (row >> 2)*64 + col*4 + (row & 3)] = v;
    }
    __syncthreads();

    const float4* w0 = (const float4*)(sm + OFF_W + 0*MATW);
    const float4* w1 = (const float4*)(sm + OFF_W + 1*MATW);
    const float4* w2 = (const float4*)(sm + OFF_W + 2*MATW);
    const float4* w3 = (const float4*)(sm + OFF_W + 3*MATW);
    const float4* aZ  = (const float4*)(sm + OFF_Z);
    const float4* aH0 = (const float4*)(sm + OFF_H0);
    const float4* aH1 = (const float4*)(sm + OFF_H1);
    const float bi0 = sm[OFF_B + 0*ROWS + r];
    const float bi1 = sm[OFF_B + 1*ROWS + r];
    const float bi2 = sm[OFF_B + 2*ROWS + r];
    const float bi3 = sm[OFF_B + 3*ROWS + r];
    const float wt0 = sm[OFF_W + 64*128 + r*4 + 0];   // W_in x-tail (k=256..258)
    const float wt1 = sm[OFF_W + 64*128 + r*4 + 1];
    const float wt2 = sm[OFF_W + 64*128 + r*4 + 2];

    // ---- main Euler loop: 4 rendezvous per step ----
    for (int s = 0; s < NSTEPS; s++) {
        const uint32_t ph = (uint32_t)(s & 1);
        const uint32_t pz = ph ^ 1u;

        // L1: z -> h0   (bar3 = Z ready from previous step)
        if (s) { mb_wait(MBA(3), pz); if (lead) mb_arm(MBA(3), TXB); }
        {
            float3 xa = eval_x(cA, t);
            float3 xb = eval_x(cB, t);
            float2 v = dot_i2(w0, aZ, r, cA);
            float vA = lipswish(v.x + wt0*xa.x + wt1*xa.y + wt2*xa.z + bi0);
            float vB = lipswish(v.y + wt0*xb.x + wt1*xb.y + wt2*xb.z + bi0);
            scatter(pb, 0, (uint32_t)OFF_H0 + zw + (uint32_t)cA*4, vA);
            scatter(pb, 0, (uint32_t)OFF_H0 + zw + (uint32_t)cB*4, vB);
        }
        // L2: h0 -> h1
        mb_wait(MBA(0), ph); if (lead) mb_arm(MBA(0), TXB);
        {
            float2 v = dot_i2(w1, aH0, r, cA);
            scatter(pb, 1, (uint32_t)OFF_H1 + zw + (uint32_t)cA*4, lipswish(v.x + bi1));
            scatter(pb, 1, (uint32_t)OFF_H1 + zw + (uint32_t)cB*4, lipswish(v.y + bi1));
        }
        // L3: h1 -> h0'  (H0 overwrite safe: bar1 full => all warps read H0)
        mb_wait(MBA(1), ph); if (lead) mb_arm(MBA(1), TXB);
        {
            float2 v = dot_i2(w2, aH1, r, cA);
            scatter(pb, 2, (uint32_t)OFF_H0 + zw + (uint32_t)cA*4, lipswish(v.x + bi2));
            scatter(pb, 2, (uint32_t)OFF_H0 + zw + (uint32_t)cB*4, lipswish(v.y + bi2));
        }
        // L4: z += dt * tanh(W_out @ h0')  (Z overwrite safe: bar2 full => L1 reads done)
        mb_wait(MBA(2), ph); if (lead) mb_arm(MBA(2), TXB);
        {
            float2 v = dot_i2(w3, aH0, r, cA);
            float fA = tanhf(v.x + bi3);
            float fB = tanhf(v.y + bi3);
            float zA = sm[OFF_Z + (int)zw + cA*4];
            float zB = sm[OFF_Z + (int)zw + cB*4];
            scatter(pb, 3, (uint32_t)OFF_Z + zw + (uint32_t)cA*4, fmaf(dt, fA, zA));
            scatter(pb, 3, (uint32_t)OFF_Z + zw + (uint32_t)cB*4, fmaf(dt, fB, zB));
        }
        t = t + dt;
    }

    // ---- final z arrivals (last send at s=379 -> parity 1) ----
    mb_wait(MBA(3), 1u);

    // ---- classifier hidden: relu(Wc1 @ z + bc1) -> H0 via bar0 (completion #381, parity 0) ----
    {
        const float4* wg = (const float4*)(Wc1 + R*HD);
        const float bi4 = __ldg(bc1 + R);
        float2 s0 = {0,0}, s1 = {0,0}, s2 = {0,0}, s3 = {0,0};
#pragma unroll 8
        for (int k = 0; k < 64; k++) {
            float4 wv = __ldg(wg + k);
            float4 aa = aZ[(k << 4) + cA];
            float4 ab = aZ[(k << 4) + cB];
            float2 wlo = make_float2(wv.x, wv.y), whi = make_float2(wv.z, wv.w);
            s0 = ffma2(wlo, make_float2(aa.x, aa.y), s0);
            s1 = ffma2(whi, make_float2(aa.z, aa.w), s1);
            s2 = ffma2(wlo, make_float2(ab.x, ab.y), s2);
            s3 = ffma2(whi, make_float2(ab.z, ab.w), s3);
        }
        float vA = fmaxf((s0.x + s0.y) + (s1.x + s1.y) + bi4, 0.0f);
        float vB = fmaxf((s2.x + s2.y) + (s3.x + s3.y) + bi4, 0.0f);
        scatter(pb, 0, (uint32_t)OFF_H0 + zw + (uint32_t)cA*4, vA);
        scatter(pb, 0, (uint32_t)OFF_H0 + zw + (uint32_t)cB*4, vB);
    }
    mb_wait(MBA(0), 0u);

    // ---- out = Wc2 @ h + bc2 (rank 0; 160 items) ----
    if (rank == 0 && tid < BPC*NCLASS) {
        int b = tid / NCLASS, cls = tid % NCLASS;
        const float4* wr = (const float4*)(Wc2 + cls*HD);
        float2 s0 = {0,0}, s1 = {0,0};
#pragma unroll 8
        for (int k = 0; k < 64; k++) {
            float4 w = __ldg(wr + k);
            float4 h = aH0[(k << 4) + b];
            s0 = ffma2(make_float2(w.x, w.y), make_float2(h.x, h.y), s0);
            s1 = ffma2(make_float2(w.z, w.w), make_float2(h.z, h.w), s1);
        }
        out[(cl*BPC + b)*NCLASS + cls] = __ldg(bc2 + cls) + (s0.x + s0.y) + (s1.x + s1.y);
    }

    cluster_bar();   // no CTA exits while peers may still write its smem
}

// ---------------- launch ----------------
extern "C" void kernel_launch(void* const* d_in, const int* in_sizes, int n_in,
                              void* d_out, int out_size) {
    (void)in_sizes; (void)n_in; (void)out_size;
    cudaFuncSetAttribute(ncde_kernel, cudaFuncAttributeMaxDynamicSharedMemorySize, SMEM_BYTES);

    cudaLaunchConfig_t cfg = {};
    cfg.gridDim  = dim3(NBLK, 1, 1);
    cfg.blockDim = dim3(NTHR, 1, 1);
    cfg.dynamicSmemBytes = SMEM_BYTES;
    cfg.stream = 0;

    cudaLaunchAttribute attrs[1];
    attrs[0].id = cudaLaunchAttributeClusterDimension;
    attrs[0].val.clusterDim.x = CSZ;
    attrs[0].val.clusterDim.y = 1;
    attrs[0].val.clusterDim.z = 1;
    cfg.attrs = attrs;
    cfg.numAttrs = 1;

    cudaLaunchKernelEx(&cfg, ncde_kernel,
        (const float*)d_in[0],  (const float*)d_in[1],
        (const float*)d_in[2],  (const float*)d_in[3],
        (const float*)d_in[4],  (const float*)d_in[5],
        (const float*)d_in[6],  (const float*)d_in[7],
        (const float*)d_in[8],  (const float*)d_in[9],
        (const float*)d_in[10], (const float*)d_in[11],
        (const float*)d_in[12], (const float*)d_in[13],
        (float*)d_out);
}

// round 14
// speedup vs baseline: 2.7671x; 1.6625x over previous
#include <cuda_runtime.h>
#include <cstdint>

#define NCTA    64
#define NTHR    512
#define COLS    4          // batch columns per CTA (64*4 = 256)
#define HD      256
#define DIM     3
#define LT      20
#define NCLASS  10
#define NSTEPS  380

// packed weights: k4-interleaved [k4][256 rows] float4
// concat: W_in(65 k4, zero-padded K 259->260) | W_h0(64) | W_h1(64) | W_out(64) | Wc1(64)
#define OFFP_IN   0
#define OFFP_H0   (65*256)
#define OFFP_H1   (129*256)
#define OFFP_OUT  (193*256)
#define OFFP_C1   (257*256)
#define NPACK     (321*256)
__device__ float4 g_wpack[NPACK];   // 1.31 MB static scratch

// ---------------- helpers ----------------
__device__ __forceinline__ float2 ffma2(float2 a, float2 b, float2 c) {
    float2 d;
    asm("fma.rn.f32x2 %0, %1, %2, %3;"
        : "=l"(*(unsigned long long*)&d)
        : "l"(*(unsigned long long*)&a),
          "l"(*(unsigned long long*)&b),
          "l"(*(unsigned long long*)&c));
    return d;
}
__device__ __forceinline__ float lipswish(float x) {
    return 0.909f * x / (1.0f + __expf(-x));
}

// ---------------- repack kernel (R7-proven) ----------------
__global__ void repack_kernel(const float* __restrict__ W_in,
                              const float* __restrict__ W_hh,
                              const float* __restrict__ W_out,
                              const float* __restrict__ Wc1) {
    int b = blockIdx.x;       // global k4 index across concatenated matrices
    int r = threadIdx.x;      // row 0..255
    const float* src; int k4; int K; int base;
    if (b < 65)       { src = W_in;          k4 = b;       K = 259; base = OFFP_IN;  }
    else if (b < 129) { src = W_hh;          k4 = b - 65;  K = 256; base = OFFP_H0;  }
    else if (b < 193) { src = W_hh + HD*HD;  k4 = b - 129; K = 256; base = OFFP_H1;  }
    else if (b < 257) { src = W_out;         k4 = b - 193; K = 256; base = OFFP_OUT; }
    else              { src = Wc1;           k4 = b - 257; K = 256; base = OFFP_C1;  }
    float v[4];
#pragma unroll
    for (int i = 0; i < 4; i++) {
        int k = k4 * 4 + i;
        v[i] = (k < K) ? src[r * K + k] : 0.0f;
    }
    g_wpack[base + k4 * 256 + r] = make_float4(v[0], v[1], v[2], v[3]);
}

// partial dot for my row r over k4 in [K4B, K4E), all 4 columns
template<int K4B, int K4E>
__device__ __forceinline__ void partial_dot(const float4* __restrict__ wp,
                                            const float* __restrict__ act,
                                            int r, float* __restrict__ out) {
    float2 aL[4], aH[4];
#pragma unroll
    for (int c = 0; c < 4; c++) { aL[c] = make_float2(0.f,0.f); aH[c] = make_float2(0.f,0.f); }
#pragma unroll 8
    for (int k4 = K4B; k4 < K4E; k4++) {
        float4 wv = __ldg(wp + (k4 << 8) + r);       // coalesced 512B/warp, L2-hit
        float2 wlo = make_float2(wv.x, wv.y), whi = make_float2(wv.z, wv.w);
#pragma unroll
        for (int c = 0; c < 4; c++) {
            float4 av = *(const float4*)(act + (k4 << 4) + (c << 2)); // LDS.128 broadcast
            aL[c] = ffma2(wlo, make_float2(av.x, av.y), aL[c]);
            aH[c] = ffma2(whi, make_float2(av.z, av.w), aH[c]);
        }
    }
#pragma unroll
    for (int c = 0; c < 4; c++)
        out[c] = (aL[c].x + aL[c].y) + (aH[c].x + aH[c].y);
}

// ---------------- main kernel: zero cross-CTA communication ----------------
__global__ void __launch_bounds__(NTHR)
ncde_stream(const float* __restrict__ coeffs, const float* __restrict__ times_g,
            const float* __restrict__ W_init, const float* __restrict__ b_init,
            const float* __restrict__ b_in,   const float* __restrict__ b_hh,
            const float* __restrict__ b_out,  const float* __restrict__ bc1,
            const float* __restrict__ Wc2,    const float* __restrict__ bc2,
            float* __restrict__ out) {
    __shared__ float sT[LT];
    __shared__ float sB[5*HD];        // b_in | b_h0 | b_h1 | b_out | bc1
    __shared__ float Z [65*16];       // [k4][4c][4]; k4=64 = x(t) slot
    __shared__ float A0[64*16];
    __shared__ float A1[64*16];
    __shared__ float4 P[HD];          // kh1 partial sums, one float4 (4 cols) per row

    const int tid = threadIdx.x;
    const int r   = tid & 255;        // my output row
    const int kh  = tid >> 8;         // K-half: 0 -> low k4, 1 -> high k4 (+finalize on kh0)
    const int gb  = blockIdx.x * COLS;

    if (tid < LT) sT[tid] = times_g[tid];
    {
        const float* bs[5] = {b_in, b_hh, b_hh + HD, b_out, bc1};
        for (int i = tid; i < 5*HD; i += NTHR) sB[i] = bs[i >> 8][i & 255];
    }
    __syncthreads();

    const float tstart = sT[0];
    const float dt = (sT[LT-1] - tstart) / (float)NSTEPS;
    float t = tstart;

    // write x(t) for my column (tid<4) into Z block 64
    auto write_x = [&](float tt) {
        if (tid < COLS) {
            int idx = 0;
#pragma unroll
            for (int i = 1; i <= LT-2; i++) idx = (sT[i] <= tt) ? i : idx;
            float ta = sT[idx], tb = sT[idx+1];
            float w = (tt - ta) / (tb - ta), om = 1.0f - w;
            const float* c0 = coeffs + ((gb + tid)*LT + idx)*DIM;
            float* xs = &Z[64*16 + tid*4];
            xs[0] = c0[0]*om + c0[DIM+0]*w;
            xs[1] = c0[1]*om + c0[DIM+1]*w;
            xs[2] = c0[2]*om + c0[DIM+2]*w;
            xs[3] = 0.0f;
        }
    };

    // ---- init: x(t0), then z0 = W_init @ x + b_init (kh0 thread r -> row r, 4 cols) ----
    write_x(t);
    __syncthreads();
    if (kh == 0) {
        float wa = __ldg(W_init + r*DIM+0), wb = __ldg(W_init + r*DIM+1),
              wc = __ldg(W_init + r*DIM+2), bb = __ldg(b_init + r);
        int zi = ((r >> 2) << 4) + (r & 3);
#pragma unroll
        for (int c = 0; c < COLS; c++) {
            const float* xs = &Z[64*16 + c*4];
            Z[zi + (c << 2)] = bb + wa*xs[0] + wb*xs[1] + wc*xs[2];
        }
    }
    __syncthreads();

    const float4* wpIN  = g_wpack + OFFP_IN;
    const float4* wpH0  = g_wpack + OFFP_H0;
    const float4* wpH1  = g_wpack + OFFP_H1;
    const float4* wpOUT = g_wpack + OFFP_OUT;
    const float b0 = sB[0*HD + r], b1 = sB[1*HD + r],
                b2 = sB[2*HD + r], b3 = sB[3*HD + r], b4 = sB[4*HD + r];
    const int ai = ((r >> 2) << 4) + (r & 3);    // interleaved base for my row
    float p[4];

    // ---- main Euler loop: CTA-local, 8 __syncthreads per step, no clusters ----
    for (int s = 0; s < NSTEPS; s++) {
        // L1: lipswish(W_in @ [z;x] + b_in) -> A0   (65 k4 incl. x-tail)
        if (kh) { partial_dot<33,65>(wpIN, Z, r, p); P[r] = make_float4(p[0],p[1],p[2],p[3]); }
        else    { partial_dot<0,33>(wpIN, Z, r, p); }
        __syncthreads();
        if (!kh) {
            float4 q = P[r];
            A0[ai +  0] = lipswish(p[0] + q.x + b0);
            A0[ai +  4] = lipswish(p[1] + q.y + b0);
            A0[ai +  8] = lipswish(p[2] + q.z + b0);
            A0[ai + 12] = lipswish(p[3] + q.w + b0);
        }
        __syncthreads();

        // L2: -> A1
        if (kh) { partial_dot<32,64>(wpH0, A0, r, p); P[r] = make_float4(p[0],p[1],p[2],p[3]); }
        else    { partial_dot<0,32>(wpH0, A0, r, p); }
        __syncthreads();
        if (!kh) {
            float4 q = P[r];
            A1[ai +  0] = lipswish(p[0] + q.x + b1);
            A1[ai +  4] = lipswish(p[1] + q.y + b1);
            A1[ai +  8] = lipswish(p[2] + q.z + b1);
            A1[ai + 12] = lipswish(p[3] + q.w + b1);
        }
        __syncthreads();

        // L3: -> A0
        if (kh) { partial_dot<32,64>(wpH1, A1, r, p); P[r] = make_float4(p[0],p[1],p[2],p[3]); }
        else    { partial_dot<0,32>(wpH1, A1, r, p); }
        __syncthreads();
        if (!kh) {
            float4 q = P[r];
            A0[ai +  0] = lipswish(p[0] + q.x + b2);
            A0[ai +  4] = lipswish(p[1] + q.y + b2);
            A0[ai +  8] = lipswish(p[2] + q.z + b2);
            A0[ai + 12] = lipswish(p[3] + q.w + b2);
        }
        __syncthreads();

        // L4: z += dt * tanh(W_out @ h + b_out); then x(t+dt)
        if (kh) { partial_dot<32,64>(wpOUT, A0, r, p); P[r] = make_float4(p[0],p[1],p[2],p[3]); }
        else    { partial_dot<0,32>(wpOUT, A0, r, p); }
        __syncthreads();
        t = t + dt;
        if (!kh) {
            float4 q = P[r];
            Z[ai +  0] = fmaf(dt, tanhf(p[0] + q.x + b3), Z[ai +  0]);
            Z[ai +  4] = fmaf(dt, tanhf(p[1] + q.y + b3), Z[ai +  4]);
            Z[ai +  8] = fmaf(dt, tanhf(p[2] + q.z + b3), Z[ai +  8]);
            Z[ai + 12] = fmaf(dt, tanhf(p[3] + q.w + b3), Z[ai + 12]);
        }
        write_x(t);
        __syncthreads();
    }

    // ---- classifier hidden: relu(Wc1 @ z + bc1) -> A0 ----
    {
        const float4* wpC1 = g_wpack + OFFP_C1;
        if (kh) { partial_dot<32,64>(wpC1, Z, r, p); P[r] = make_float4(p[0],p[1],p[2],p[3]); }
        else    { partial_dot<0,32>(wpC1, Z, r, p); }
        __syncthreads();
        if (!kh) {
            float4 q = P[r];
            A0[ai +  0] = fmaxf(p[0] + q.x + b4, 0.0f);
            A0[ai +  4] = fmaxf(p[1] + q.y + b4, 0.0f);
            A0[ai +  8] = fmaxf(p[2] + q.z + b4, 0.0f);
            A0[ai + 12] = fmaxf(p[3] + q.w + b4, 0.0f);
        }
        __syncthreads();
    }

    // ---- out = Wc2 @ h + bc2 : 40 dots per CTA ----
    if (tid < COLS * NCLASS) {
        int c = tid / NCLASS, cls = tid % NCLASS;
        const float4* wr = (const float4*)(Wc2 + cls * HD);
        float2 se = {0,0}, so = {0,0};
#pragma unroll 8
        for (int k4 = 0; k4 < 64; k4++) {
            float4 w = __ldg(wr + k4);
            float4 h = *(const float4*)(&A0[(k4 << 4) + (c << 2)]);
            se = ffma2(make_float2(w.x, w.y), make_float2(h.x, h.y), se);
            so = ffma2(make_float2(w.z, w.w), make_float2(h.z, h.w), so);
        }
        out[(gb + c) * NCLASS + cls] = __ldg(bc2 + cls) + (se.x + se.y) + (so.x + so.y);
    }
}

// ---------------- launch ----------------
extern "C" void kernel_launch(void* const* d_in, const int* in_sizes, int n_in,
                              void* d_out, int out_size) {
    (void)in_sizes; (void)n_in; (void)out_size;
    const float* coeffs = (const float*)d_in[0];
    const float* times  = (const float*)d_in[1];
    const float* W_init = (const float*)d_in[2];
    const float* b_init = (const float*)d_in[3];
    const float* W_in   = (const float*)d_in[4];
    const float* b_in   = (const float*)d_in[5];
    const float* W_hh   = (const float*)d_in[6];
    const float* b_hh   = (const float*)d_in[7];
    const float* W_out  = (const float*)d_in[8];
    const float* b_out  = (const float*)d_in[9];
    const float* Wc1    = (const float*)d_in[10];
    const float* bc1    = (const float*)d_in[11];
    const float* Wc2    = (const float*)d_in[12];
    const float* bc2    = (const float*)d_in[13];

    repack_kernel<<<321, 256>>>(W_in, W_hh, W_out, Wc1);
    ncde_stream<<<NCTA, NTHR>>>(coeffs, times, W_init, b_init,
                                b_in, b_hh, b_out, bc1, Wc2, bc2,
                                (float*)d_out);
}

// round 15
// speedup vs baseline: 2.8412x; 1.0268x over previous
#include <cuda_runtime.h>
#include <cstdint>

#define NCTA    64
#define NTHR    512
#define COLS    4          // batch columns per CTA (64*4 = 256)
#define HD      256
#define DIM     3
#define LT      20
#define NCLASS  10
#define NSTEPS  380
#define AST     260        // activation column stride (floats); c*260 words = 16B aligned

// packed weights: k4-interleaved [k4][256 rows] float4
// concat: W_in(65 k4, zero-padded K 259->260) | W_h0(64) | W_h1(64) | W_out(64) | Wc1(64)
#define OFFP_IN   0
#define OFFP_H0   (65*256)
#define OFFP_H1   (129*256)
#define OFFP_OUT  (193*256)
#define OFFP_C1   (257*256)
#define NPACK     (321*256)
__device__ float4 g_wpack[NPACK];   // 1.31 MB static scratch

// ---------------- helpers ----------------
__device__ __forceinline__ float2 ffma2(float2 a, float2 b, float2 c) {
    float2 d;
    asm("fma.rn.f32x2 %0, %1, %2, %3;"
        : "=l"(*(unsigned long long*)&d)
        : "l"(*(unsigned long long*)&a),
          "l"(*(unsigned long long*)&b),
          "l"(*(unsigned long long*)&c));
    return d;
}
__device__ __forceinline__ float lipswish(float x) {
    return 0.909f * x / (1.0f + __expf(-x));
}

// ---------------- repack kernel (R13-proven, unchanged) ----------------
__global__ void repack_kernel(const float* __restrict__ W_in,
                              const float* __restrict__ W_hh,
                              const float* __restrict__ W_out,
                              const float* __restrict__ Wc1) {
    int b = blockIdx.x;       // global k4 index across concatenated matrices
    int r = threadIdx.x;      // row 0..255
    const float* src; int k4; int K; int base;
    if (b < 65)       { src = W_in;          k4 = b;       K = 259; base = OFFP_IN;  }
    else if (b < 129) { src = W_hh;          k4 = b - 65;  K = 256; base = OFFP_H0;  }
    else if (b < 193) { src = W_hh + HD*HD;  k4 = b - 129; K = 256; base = OFFP_H1;  }
    else if (b < 257) { src = W_out;         k4 = b - 193; K = 256; base = OFFP_OUT; }
    else              { src = Wc1;           k4 = b - 257; K = 256; base = OFFP_C1;  }
    float v[4];
#pragma unroll
    for (int i = 0; i < 4; i++) {
        int k = k4 * 4 + i;
        v[i] = (k < K) ? src[r * K + k] : 0.0f;
    }
    g_wpack[base + k4 * 256 + r] = make_float4(v[0], v[1], v[2], v[3]);
}

// partial dot: rows (r0, r0+128), all 4 cols, k4 in [k4b, k4e); stores 2 float4 partials
__device__ __forceinline__ void pdot(const float4* __restrict__ wp,
                                     const float* __restrict__ act,
                                     int k4b, int k4e, int r0,
                                     float4* __restrict__ pslot) {
    float2 aL0[4], aH0[4], aL1[4], aH1[4];
#pragma unroll
    for (int c = 0; c < 4; c++) {
        aL0[c] = make_float2(0.f,0.f); aH0[c] = make_float2(0.f,0.f);
        aL1[c] = make_float2(0.f,0.f); aH1[c] = make_float2(0.f,0.f);
    }
#pragma unroll 4
    for (int k4 = k4b; k4 < k4e; k4++) {
        float4 w0 = __ldg(wp + (k4 << 8) + r0);         // coalesced 512B/warp
        float4 w1 = __ldg(wp + (k4 << 8) + r0 + 128);
        float2 w0l = make_float2(w0.x, w0.y), w0h = make_float2(w0.z, w0.w);
        float2 w1l = make_float2(w1.x, w1.y), w1h = make_float2(w1.z, w1.w);
#pragma unroll
        for (int c = 0; c < 4; c++) {
            float4 av = *(const float4*)(act + c*AST + (k4 << 2));  // broadcast LDS.128
            float2 al = make_float2(av.x, av.y), ah = make_float2(av.z, av.w);
            aL0[c] = ffma2(w0l, al, aL0[c]); aH0[c] = ffma2(w0h, ah, aH0[c]);
            aL1[c] = ffma2(w1l, al, aL1[c]); aH1[c] = ffma2(w1h, ah, aH1[c]);
        }
    }
    float4 p0, p1;
    p0.x = (aL0[0].x + aL0[0].y) + (aH0[0].x + aH0[0].y);
    p0.y = (aL0[1].x + aL0[1].y) + (aH0[1].x + aH0[1].y);
    p0.z = (aL0[2].x + aL0[2].y) + (aH0[2].x + aH0[2].y);
    p0.w = (aL0[3].x + aL0[3].y) + (aH0[3].x + aH0[3].y);
    p1.x = (aL1[0].x + aL1[0].y) + (aH1[0].x + aH1[0].y);
    p1.y = (aL1[1].x + aL1[1].y) + (aH1[1].x + aH1[1].y);
    p1.z = (aL1[2].x + aL1[2].y) + (aH1[2].x + aH1[2].y);
    p1.w = (aL1[3].x + aL1[3].y) + (aH1[3].x + aH1[3].y);
    pslot[0] = p0;
    pslot[1] = p1;
}

// ---------------- main kernel: zero cross-CTA communication ----------------
__global__ void __launch_bounds__(NTHR)
ncde_stream(const float* __restrict__ coeffs, const float* __restrict__ times_g,
            const float* __restrict__ W_init, const float* __restrict__ b_init,
            const float* __restrict__ b_in,   const float* __restrict__ b_hh,
            const float* __restrict__ b_out,  const float* __restrict__ bc1,
            const float* __restrict__ Wc2,    const float* __restrict__ bc2,
            float* __restrict__ out) {
    __shared__ float  sT[LT];
    __shared__ float  sB[5*HD];          // b_in | b_h0 | b_h1 | b_out | bc1
    __shared__ float  Z [COLS*AST];      // [c][260]: rows 0..255, x at 256..258, 0 at 259
    __shared__ float  A0[COLS*AST];
    __shared__ float  A1[COLS*AST];
    __shared__ float4 P4[4*128*2];       // [kq][rp][rr] partials (4 cols each) = 16 KB

    const int tid = threadIdx.x;
    const int rp  = tid & 127;           // row-pair index (rows rp, rp+128)
    const int kq  = tid >> 7;            // K-quarter 0..3
    const int gb  = blockIdx.x * COLS;
    float4* myP = &P4[((kq << 7) + rp) * 2];

    if (tid < LT) sT[tid] = times_g[tid];
    {
        const float* bs[5] = {b_in, b_hh, b_hh + HD, b_out, bc1};
        for (int i = tid; i < 5*HD; i += NTHR) sB[i] = bs[i >> 8][i & 255];
    }
    __syncthreads();

    const float tstart = sT[0];
    const float dt = (sT[LT-1] - tstart) / (float)NSTEPS;
    float t = tstart;

    // x(t) writer for one column (runs on threads 256..259 in-loop, tid<4 at init)
    auto write_x = [&](int col, float tt) {
        int idx = 0;
#pragma unroll
        for (int i = 1; i <= LT-2; i++) idx = (sT[i] <= tt) ? i : idx;
        float ta = sT[idx], tb = sT[idx+1];
        float w = (tt - ta) / (tb - ta), om = 1.0f - w;
        const float* c0 = coeffs + ((gb + col)*LT + idx)*DIM;
        float* xs = &Z[col*AST + 256];
        xs[0] = c0[0]*om + c0[DIM+0]*w;
        xs[1] = c0[1]*om + c0[DIM+1]*w;
        xs[2] = c0[2]*om + c0[DIM+2]*w;
        xs[3] = 0.0f;
    };

    // ---- init: x(t0), then z0 = W_init @ x + b_init ----
    if (tid < COLS) write_x(tid, t);
    __syncthreads();
    if (tid < HD) {
        int row = tid;
        float wa = __ldg(W_init + row*DIM+0), wb = __ldg(W_init + row*DIM+1),
              wc = __ldg(W_init + row*DIM+2), bb = __ldg(b_init + row);
#pragma unroll
        for (int c = 0; c < COLS; c++) {
            const float* xs = &Z[c*AST + 256];
            Z[c*AST + row] = bb + wa*xs[0] + wb*xs[1] + wc*xs[2];
        }
    }
    __syncthreads();

    const float4* wpIN  = g_wpack + OFFP_IN;
    const float4* wpH0  = g_wpack + OFFP_H0;
    const float4* wpH1  = g_wpack + OFFP_H1;
    const float4* wpOUT = g_wpack + OFFP_OUT;
    // K-quarter bounds: L1 (65 blocks incl. x-tail), hidden layers (64 blocks)
    const int b65lo = (kq == 0) ? 0 : 17 + (kq-1)*16;   // {0,17,33,49}
    const int b65hi = 17 + kq*16;                        // {17,33,49,65}
    const int b64lo = kq << 4, b64hi = (kq+1) << 4;

    // ---- main Euler loop: CTA-local, 8 __syncthreads per step ----
    for (int s = 0; s < NSTEPS; s++) {
        // L1: lipswish(W_in @ [z;x] + b_in) -> A0
        pdot(wpIN, Z, b65lo, b65hi, rp, myP);
        __syncthreads();
        if (tid < HD) {
            int row = tid, rp2 = row & 127, rr = row >> 7;
            float4 v0 = P4[((0<<7) + rp2)*2 + rr], v1 = P4[((1<<7) + rp2)*2 + rr];
            float4 v2 = P4[((2<<7) + rp2)*2 + rr], v3 = P4[((3<<7) + rp2)*2 + rr];
            float b = sB[0*HD + row];
            A0[0*AST + row] = lipswish(v0.x + v1.x + v2.x + v3.x + b);
            A0[1*AST + row] = lipswish(v0.y + v1.y + v2.y + v3.y + b);
            A0[2*AST + row] = lipswish(v0.z + v1.z + v2.z + v3.z + b);
            A0[3*AST + row] = lipswish(v0.w + v1.w + v2.w + v3.w + b);
        }
        __syncthreads();

        // L2: -> A1
        pdot(wpH0, A0, b64lo, b64hi, rp, myP);
        __syncthreads();
        if (tid < HD) {
            int row = tid, rp2 = row & 127, rr = row >> 7;
            float4 v0 = P4[((0<<7) + rp2)*2 + rr], v1 = P4[((1<<7) + rp2)*2 + rr];
            float4 v2 = P4[((2<<7) + rp2)*2 + rr], v3 = P4[((3<<7) + rp2)*2 + rr];
            float b = sB[1*HD + row];
            A1[0*AST + row] = lipswish(v0.x + v1.x + v2.x + v3.x + b);
            A1[1*AST + row] = lipswish(v0.y + v1.y + v2.y + v3.y + b);
            A1[2*AST + row] = lipswish(v0.z + v1.z + v2.z + v3.z + b);
            A1[3*AST + row] = lipswish(v0.w + v1.w + v2.w + v3.w + b);
        }
        __syncthreads();

        // L3: -> A0
        pdot(wpH1, A1, b64lo, b64hi, rp, myP);
        __syncthreads();
        if (tid < HD) {
            int row = tid, rp2 = row & 127, rr = row >> 7;
            float4 v0 = P4[((0<<7) + rp2)*2 + rr], v1 = P4[((1<<7) + rp2)*2 + rr];
            float4 v2 = P4[((2<<7) + rp2)*2 + rr], v3 = P4[((3<<7) + rp2)*2 + rr];
            float b = sB[2*HD + row];
            A0[0*AST + row] = lipswish(v0.x + v1.x + v2.x + v3.x + b);
            A0[1*AST + row] = lipswish(v0.y + v1.y + v2.y + v3.y + b);
            A0[2*AST + row] = lipswish(v0.z + v1.z + v2.z + v3.z + b);
            A0[3*AST + row] = lipswish(v0.w + v1.w + v2.w + v3.w + b);
        }
        __syncthreads();

        // L4: z += dt * tanh(W_out @ h + b_out); x(t+dt) written by threads 256..259
        pdot(wpOUT, A0, b64lo, b64hi, rp, myP);
        __syncthreads();
        t += dt;
        if (tid < HD) {
            int row = tid, rp2 = row & 127, rr = row >> 7;
            float4 v0 = P4[((0<<7) + rp2)*2 + rr], v1 = P4[((1<<7) + rp2)*2 + rr];
            float4 v2 = P4[((2<<7) + rp2)*2 + rr], v3 = P4[((3<<7) + rp2)*2 + rr];
            float b = sB[3*HD + row];
            Z[0*AST + row] = fmaf(dt, tanhf(v0.x + v1.x + v2.x + v3.x + b), Z[0*AST + row]);
            Z[1*AST + row] = fmaf(dt, tanhf(v0.y + v1.y + v2.y + v3.y + b), Z[1*AST + row]);
            Z[2*AST + row] = fmaf(dt, tanhf(v0.z + v1.z + v2.z + v3.z + b), Z[2*AST + row]);
            Z[3*AST + row] = fmaf(dt, tanhf(v0.w + v1.w + v2.w + v3.w + b), Z[3*AST + row]);
        } else if (tid < HD + COLS) {
            write_x(tid - HD, t);
        }
        __syncthreads();
    }

    // ---- classifier hidden: relu(Wc1 @ z + bc1) -> A0 ----
    pdot(g_wpack + OFFP_C1, Z, b64lo, b64hi, rp, myP);
    __syncthreads();
    if (tid < HD) {
        int row = tid, rp2 = row & 127, rr = row >> 7;
        float4 v0 = P4[((0<<7) + rp2)*2 + rr], v1 = P4[((1<<7) + rp2)*2 + rr];
        float4 v2 = P4[((2<<7) + rp2)*2 + rr], v3 = P4[((3<<7) + rp2)*2 + rr];
        float b = sB[4*HD + row];
        A0[0*AST + row] = fmaxf(v0.x + v1.x + v2.x + v3.x + b, 0.0f);
        A0[1*AST + row] = fmaxf(v0.y + v1.y + v2.y + v3.y + b, 0.0f);
        A0[2*AST + row] = fmaxf(v0.z + v1.z + v2.z + v3.z + b, 0.0f);
        A0[3*AST + row] = fmaxf(v0.w + v1.w + v2.w + v3.w + b, 0.0f);
    }
    __syncthreads();

    // ---- out = Wc2 @ h + bc2 : 40 dots per CTA ----
    if (tid < COLS * NCLASS) {
        int c = tid / NCLASS, cls = tid % NCLASS;
        const float4* wr = (const float4*)(Wc2 + cls * HD);
        const float* hb = &A0[c*AST];
        float2 se = {0,0}, so = {0,0};
#pragma unroll 8
        for (int k4 = 0; k4 < 64; k4++) {
            float4 w = __ldg(wr + k4);
            float4 h = *(const float4*)(hb + (k4 << 2));
            se = ffma2(make_float2(w.x, w.y), make_float2(h.x, h.y), se);
            so = ffma2(make_float2(w.z, w.w), make_float2(h.z, h.w), so);
        }
        out[(gb + c) * NCLASS + cls] = __ldg(bc2 + cls) + (se.x + se.y) + (so.x + so.y);
    }
}

// ---------------- launch ----------------
extern "C" void kernel_launch(void* const* d_in, const int* in_sizes, int n_in,
                              void* d_out, int out_size) {
    (void)in_sizes; (void)n_in; (void)out_size;
    const float* coeffs = (const float*)d_in[0];
    const float* times  = (const float*)d_in[1];
    const float* W_init = (const float*)d_in[2];
    const float* b_init = (const float*)d_in[3];
    const float* W_in   = (const float*)d_in[4];
    const float* b_in   = (const float*)d_in[5];
    const float* W_hh   = (const float*)d_in[6];
    const float* b_hh   = (const float*)d_in[7];
    const float* W_out  = (const float*)d_in[8];
    const float* b_out  = (const float*)d_in[9];
    const float* Wc1    = (const float*)d_in[10];
    const float* bc1    = (const float*)d_in[11];
    const float* Wc2    = (const float*)d_in[12];
    const float* bc2    = (const float*)d_in[13];

    repack_kernel<<<321, 256>>>(W_in, W_hh, W_out, Wc1);
    ncde_stream<<<NCTA, NTHR>>>(coeffs, times, W_init, b_init,
                                b_in, b_hh, b_out, bc1, Wc2, bc2,
                                (float*)d_out);
}

// round 16
// speedup vs baseline: 2.9342x; 1.0328x over previous
#include <cuda_runtime.h>
#include <cstdint>

#define NCTA    64
#define NTHR    1024
#define COLS    4          // batch columns per CTA (64*4 = 256)
#define HD      256
#define DIM     3
#define LT      20
#define NCLASS  10
#define NSTEPS  380
#define AST     260        // activation column stride (floats)

// packed weights: k4-interleaved [k4][256 rows] float4
#define OFFP_IN   0
#define OFFP_H0   (65*256)
#define OFFP_H1   (129*256)
#define OFFP_OUT  (193*256)
#define OFFP_C1   (257*256)
#define NPACK     (321*256)
__device__ float4 g_wpack[NPACK];   // 1.31 MB static scratch

// ---- dynamic smem word offsets ----
#define OFF_T   0                     // [20]
#define OFF_B   20                    // [5*256]
#define OFF_Z   (OFF_B + 5*HD)        // [4][260]
#define OFF_A0  (OFF_Z + COLS*AST)
#define OFF_A1  (OFF_A0 + COLS*AST)
#define OFF_P   (((OFF_A1 + COLS*AST) + 3) & ~3)   // float4-aligned; [8][128][2] float4
#define SMEM_WORDS (OFF_P + 8*128*2*4)
#define SMEM_BYTES (SMEM_WORDS*4)     // ~50.5 KB

// ---------------- helpers ----------------
__device__ __forceinline__ float2 ffma2(float2 a, float2 b, float2 c) {
    float2 d;
    asm("fma.rn.f32x2 %0, %1, %2, %3;"
        : "=l"(*(unsigned long long*)&d)
        : "l"(*(unsigned long long*)&a),
          "l"(*(unsigned long long*)&b),
          "l"(*(unsigned long long*)&c));
    return d;
}
__device__ __forceinline__ float lipswish(float x) {
    return 0.909f * x / (1.0f + __expf(-x));
}

// ---------------- repack kernel (R13-proven, unchanged) ----------------
__global__ void repack_kernel(const float* __restrict__ W_in,
                              const float* __restrict__ W_hh,
                              const float* __restrict__ W_out,
                              const float* __restrict__ Wc1) {
    int b = blockIdx.x;
    int r = threadIdx.x;
    const float* src; int k4; int K; int base;
    if (b < 65)       { src = W_in;          k4 = b;       K = 259; base = OFFP_IN;  }
    else if (b < 129) { src = W_hh;          k4 = b - 65;  K = 256; base = OFFP_H0;  }
    else if (b < 193) { src = W_hh + HD*HD;  k4 = b - 129; K = 256; base = OFFP_H1;  }
    else if (b < 257) { src = W_out;         k4 = b - 193; K = 256; base = OFFP_OUT; }
    else              { src = Wc1;           k4 = b - 257; K = 256; base = OFFP_C1;  }
    float v[4];
#pragma unroll
    for (int i = 0; i < 4; i++) {
        int k = k4 * 4 + i;
        v[i] = (k < K) ? src[r * K + k] : 0.0f;
    }
    g_wpack[base + k4 * 256 + r] = make_float4(v[0], v[1], v[2], v[3]);
}

// partial dot: rows (r0, r0+128), all 4 cols, k4 in [k4b, k4e)
__device__ __forceinline__ void pdot(const float4* __restrict__ wp,
                                     const float* __restrict__ act,
                                     int k4b, int k4e, int r0,
                                     float4* __restrict__ pslot) {
    float2 aL0[4], aH0[4], aL1[4], aH1[4];
#pragma unroll
    for (int c = 0; c < 4; c++) {
        aL0[c] = make_float2(0.f,0.f); aH0[c] = make_float2(0.f,0.f);
        aL1[c] = make_float2(0.f,0.f); aH1[c] = make_float2(0.f,0.f);
    }
#pragma unroll 4
    for (int k4 = k4b; k4 < k4e; k4++) {
        float4 w0 = __ldg(wp + (k4 << 8) + r0);
        float4 w1 = __ldg(wp + (k4 << 8) + r0 + 128);
        float2 w0l = make_float2(w0.x, w0.y), w0h = make_float2(w0.z, w0.w);
        float2 w1l = make_float2(w1.x, w1.y), w1h = make_float2(w1.z, w1.w);
#pragma unroll
        for (int c = 0; c < 4; c++) {
            float4 av = *(const float4*)(act + c*AST + (k4 << 2));
            float2 al = make_float2(av.x, av.y), ah = make_float2(av.z, av.w);
            aL0[c] = ffma2(w0l, al, aL0[c]); aH0[c] = ffma2(w0h, ah, aH0[c]);
            aL1[c] = ffma2(w1l, al, aL1[c]); aH1[c] = ffma2(w1h, ah, aH1[c]);
        }
    }
    float4 p0, p1;
    p0.x = (aL0[0].x + aL0[0].y) + (aH0[0].x + aH0[0].y);
    p0.y = (aL0[1].x + aL0[1].y) + (aH0[1].x + aH0[1].y);
    p0.z = (aL0[2].x + aL0[2].y) + (aH0[2].x + aH0[2].y);
    p0.w = (aL0[3].x + aL0[3].y) + (aH0[3].x + aH0[3].y);
    p1.x = (aL1[0].x + aL1[0].y) + (aH1[0].x + aH1[0].y);
    p1.y = (aL1[1].x + aL1[1].y) + (aH1[1].x + aH1[1].y);
    p1.z = (aL1[2].x + aL1[2].y) + (aH1[2].x + aH1[2].y);
    p1.w = (aL1[3].x + aL1[3].y) + (aH1[3].x + aH1[3].y);
    pslot[0] = p0;
    pslot[1] = p1;
}

// ---------------- main kernel ----------------
__global__ void __launch_bounds__(NTHR, 1)
ncde_stream(const float* __restrict__ coeffs, const float* __restrict__ times_g,
            const float* __restrict__ W_init, const float* __restrict__ b_init,
            const float* __restrict__ b_in,   const float* __restrict__ b_hh,
            const float* __restrict__ b_out,  const float* __restrict__ bc1,
            const float* __restrict__ Wc2,    const float* __restrict__ bc2,
            float* __restrict__ out) {
    extern __shared__ float sm[];
    float*  sT = sm + OFF_T;
    float*  sB = sm + OFF_B;
    float*  Z  = sm + OFF_Z;
    float*  A0 = sm + OFF_A0;
    float*  A1 = sm + OFF_A1;
    float4* P4 = (float4*)(sm + OFF_P);   // [8 kq][128 rp][2 rr]

    const int tid = threadIdx.x;
    const int rp  = tid & 127;           // row-pair (rows rp, rp+128)
    const int kq  = tid >> 7;            // K-eighth 0..7
    const int gb  = blockIdx.x * COLS;
    float4* myP = &P4[((kq << 7) + rp) * 2];

    if (tid < LT) sT[tid] = times_g[tid];
    {
        const float* bs[5] = {b_in, b_hh, b_hh + HD, b_out, bc1};
        for (int i = tid; i < 5*HD; i += NTHR) sB[i] = bs[i >> 8][i & 255];
    }
    __syncthreads();

    const float tstart = sT[0];
    const float dt = (sT[LT-1] - tstart) / (float)NSTEPS;
    float t = tstart;

    auto write_x = [&](int col, float tt) {
        int idx = 0;
#pragma unroll
        for (int i = 1; i <= LT-2; i++) idx = (sT[i] <= tt) ? i : idx;
        float ta = sT[idx], tb = sT[idx+1];
        float w = (tt - ta) / (tb - ta), om = 1.0f - w;
        const float* c0 = coeffs + ((gb + col)*LT + idx)*DIM;
        float* xs = &Z[col*AST + 256];
        xs[0] = c0[0]*om + c0[DIM+0]*w;
        xs[1] = c0[1]*om + c0[DIM+1]*w;
        xs[2] = c0[2]*om + c0[DIM+2]*w;
        xs[3] = 0.0f;
    };

    // ---- init: x(t0), then z0 = W_init @ x + b_init ----
    if (tid < COLS) write_x(tid, t);
    __syncthreads();
    if (tid < HD) {
        int row = tid;
        float wa = __ldg(W_init + row*DIM+0), wb = __ldg(W_init + row*DIM+1),
              wc = __ldg(W_init + row*DIM+2), bb = __ldg(b_init + row);
#pragma unroll
        for (int c = 0; c < COLS; c++) {
            const float* xs = &Z[c*AST + 256];
            Z[c*AST + row] = bb + wa*xs[0] + wb*xs[1] + wc*xs[2];
        }
    }
    __syncthreads();

    const float4* wpIN  = g_wpack + OFFP_IN;
    const float4* wpH0  = g_wpack + OFFP_H0;
    const float4* wpH1  = g_wpack + OFFP_H1;
    const float4* wpOUT = g_wpack + OFFP_OUT;
    // 8-way K bounds: L1 (65 blocks: 9+7*8), hidden (64 blocks: 8 each)
    const int b65lo = (kq == 0) ? 0 : 9 + (kq-1)*8;
    const int b65hi = 9 + kq*8;
    const int b64lo = kq << 3, b64hi = (kq+1) << 3;

    // finalize helper: sums 8 partials for row tid, applies f, writes dst[c*AST+row]
#define FINALIZE(DST, BIAS, FXPR)                                             \
    if (tid < HD) {                                                           \
        int row = tid, rp2 = row & 127, rr = row >> 7;                        \
        float4 acc = P4[(rp2)*2 + rr];                                        \
        _Pragma("unroll")                                                     \
        for (int q = 1; q < 8; q++) {                                         \
            float4 v = P4[((q << 7) + rp2)*2 + rr];                           \
            acc.x += v.x; acc.y += v.y; acc.z += v.z; acc.w += v.w;           \
        }                                                                     \
        float b = (BIAS);                                                     \
        { float pv = acc.x + b; DST[0*AST + row] = FXPR; }                    \
        { float pv = acc.y + b; DST[1*AST + row] = FXPR; }                    \
        { float pv = acc.z + b; DST[2*AST + row] = FXPR; }                    \
        { float pv = acc.w + b; DST[3*AST + row] = FXPR; }                    \
    }

    // ---- main Euler loop ----
    for (int s = 0; s < NSTEPS; s++) {
        // L1
        pdot(wpIN, Z, b65lo, b65hi, rp, myP);
        __syncthreads();
        FINALIZE(A0, sB[0*HD + row], lipswish(pv))
        __syncthreads();
        // L2
        pdot(wpH0, A0, b64lo, b64hi, rp, myP);
        __syncthreads();
        FINALIZE(A1, sB[1*HD + row], lipswish(pv))
        __syncthreads();
        // L3
        pdot(wpH1, A1, b64lo, b64hi, rp, myP);
        __syncthreads();
        FINALIZE(A0, sB[2*HD + row], lipswish(pv))
        __syncthreads();
        // L4 + x(t+dt)
        pdot(wpOUT, A0, b64lo, b64hi, rp, myP);
        __syncthreads();
        t += dt;
        if (tid < HD) {
            int row = tid, rp2 = row & 127, rr = row >> 7;
            float4 acc = P4[(rp2)*2 + rr];
#pragma unroll
            for (int q = 1; q < 8; q++) {
                float4 v = P4[((q << 7) + rp2)*2 + rr];
                acc.x += v.x; acc.y += v.y; acc.z += v.z; acc.w += v.w;
            }
            float b = sB[3*HD + row];
            Z[0*AST + row] = fmaf(dt, tanhf(acc.x + b), Z[0*AST + row]);
            Z[1*AST + row] = fmaf(dt, tanhf(acc.y + b), Z[1*AST + row]);
            Z[2*AST + row] = fmaf(dt, tanhf(acc.z + b), Z[2*AST + row]);
            Z[3*AST + row] = fmaf(dt, tanhf(acc.w + b), Z[3*AST + row]);
        } else if (tid < HD + COLS) {
            write_x(tid - HD, t);
        }
        __syncthreads();
    }

    // ---- classifier hidden: relu(Wc1 @ z + bc1) -> A0 ----
    pdot(g_wpack + OFFP_C1, Z, b64lo, b64hi, rp, myP);
    __syncthreads();
    FINALIZE(A0, sB[4*HD + row], fmaxf(pv, 0.0f))
    __syncthreads();

    // ---- out = Wc2 @ h + bc2 ----
    if (tid < COLS * NCLASS) {
        int c = tid / NCLASS, cls = tid % NCLASS;
        const float4* wr = (const float4*)(Wc2 + cls * HD);
        const float* hb = &A0[c*AST];
        float2 se = {0,0}, so = {0,0};
#pragma unroll 8
        for (int k4 = 0; k4 < 64; k4++) {
            float4 w = __ldg(wr + k4);
            float4 h = *(const float4*)(hb + (k4 << 2));
            se = ffma2(make_float2(w.x, w.y), make_float2(h.x, h.y), se);
            so = ffma2(make_float2(w.z, w.w), make_float2(h.z, h.w), so);
        }
        out[(gb + c) * NCLASS + cls] = __ldg(bc2 + cls) + (se.x + se.y) + (so.x + so.y);
    }
#undef FINALIZE
}

// ---------------- launch ----------------
extern "C" void kernel_launch(void* const* d_in, const int* in_sizes, int n_in,
                              void* d_out, int out_size) {
    (void)in_sizes; (void)n_in; (void)out_size;
    const float* coeffs = (const float*)d_in[0];
    const float* times  = (const float*)d_in[1];
    const float* W_init = (const float*)d_in[2];
    const float* b_init = (const float*)d_in[3];
    const float* W_in   = (const float*)d_in[4];
    const float* b_in   = (const float*)d_in[5];
    const float* W_hh   = (const float*)d_in[6];
    const float* b_hh   = (const float*)d_in[7];
    const float* W_out  = (const float*)d_in[8];
    const float* b_out  = (const float*)d_in[9];
    const float* Wc1    = (const float*)d_in[10];
    const float* bc1    = (const float*)d_in[11];
    const float* Wc2    = (const float*)d_in[12];
    const float* bc2    = (const float*)d_in[13];

    cudaFuncSetAttribute(ncde_stream, cudaFuncAttributeMaxDynamicSharedMemorySize, SMEM_BYTES);
    repack_kernel<<<321, 256>>>(W_in, W_hh, W_out, Wc1);
    ncde_stream<<<NCTA, NTHR, SMEM_BYTES>>>(coeffs, times, W_init, b_init,
                                            b_in, b_hh, b_out, bc1, Wc2, bc2,
                                            (float*)d_out);
}

// round 17
// speedup vs baseline: 4.8181x; 1.6420x over previous
#include <cuda_runtime.h>
#include <cstdint>

#define NCTA    128
#define NTHR    1024
#define COLS    2          // batch columns per CTA (128*2 = 256)
#define HD      256
#define DIM     3
#define LT      20
#define NCLASS  10
#define NSTEPS  380
#define AST     260        // activation column stride (floats)

// packed weights: k4-interleaved [k4][256 rows] float4
#define OFFP_IN   0
#define OFFP_H0   (65*256)
#define OFFP_H1   (129*256)
#define OFFP_OUT  (193*256)
#define OFFP_C1   (257*256)
#define NPACK     (321*256)
__device__ float4 g_wpack[NPACK];   // 1.31 MB static scratch

// ---------------- helpers ----------------
__device__ __forceinline__ float2 ffma2(float2 a, float2 b, float2 c) {
    float2 d;
    asm("fma.rn.f32x2 %0, %1, %2, %3;"
        : "=l"(*(unsigned long long*)&d)
        : "l"(*(unsigned long long*)&a),
          "l"(*(unsigned long long*)&b),
          "l"(*(unsigned long long*)&c));
    return d;
}
__device__ __forceinline__ float lipswish(float x) {
    return 0.909f * x / (1.0f + __expf(-x));
}

// ---------------- repack kernel (R13-proven, unchanged) ----------------
__global__ void repack_kernel(const float* __restrict__ W_in,
                              const float* __restrict__ W_hh,
                              const float* __restrict__ W_out,
                              const float* __restrict__ Wc1) {
    int b = blockIdx.x;
    int r = threadIdx.x;
    const float* src; int k4; int K; int base;
    if (b < 65)       { src = W_in;          k4 = b;       K = 259; base = OFFP_IN;  }
    else if (b < 129) { src = W_hh;          k4 = b - 65;  K = 256; base = OFFP_H0;  }
    else if (b < 193) { src = W_hh + HD*HD;  k4 = b - 129; K = 256; base = OFFP_H1;  }
    else if (b < 257) { src = W_out;         k4 = b - 193; K = 256; base = OFFP_OUT; }
    else              { src = Wc1;           k4 = b - 257; K = 256; base = OFFP_C1;  }
    float v[4];
#pragma unroll
    for (int i = 0; i < 4; i++) {
        int k = k4 * 4 + i;
        v[i] = (k < K) ? src[r * K + k] : 0.0f;
    }
    g_wpack[base + k4 * 256 + r] = make_float4(v[0], v[1], v[2], v[3]);
}

// partial dot: rows (r0, r0+128), 2 cols, k4 in [k4b, k4e)
// stores 4 scalars into P[(kq*2+col)*256 + row]
__device__ __forceinline__ void pdot(const float4* __restrict__ wp,
                                     const float* __restrict__ act,
                                     int k4b, int k4e, int r0, int kq,
                                     float* __restrict__ P) {
    float2 a00l = {0,0}, a00h = {0,0}, a01l = {0,0}, a01h = {0,0};
    float2 a10l = {0,0}, a10h = {0,0}, a11l = {0,0}, a11h = {0,0};
#pragma unroll 4
    for (int k4 = k4b; k4 < k4e; k4++) {
        float4 w0 = __ldg(wp + (k4 << 8) + r0);          // coalesced 512B/warp
        float4 w1 = __ldg(wp + (k4 << 8) + r0 + 128);
        float2 w0l = make_float2(w0.x, w0.y), w0h = make_float2(w0.z, w0.w);
        float2 w1l = make_float2(w1.x, w1.y), w1h = make_float2(w1.z, w1.w);
        float4 av0 = *(const float4*)(act + 0*AST + (k4 << 2));   // broadcast LDS.128
        float4 av1 = *(const float4*)(act + 1*AST + (k4 << 2));
        float2 a0l = make_float2(av0.x, av0.y), a0h = make_float2(av0.z, av0.w);
        float2 a1l = make_float2(av1.x, av1.y), a1h = make_float2(av1.z, av1.w);
        a00l = ffma2(w0l, a0l, a00l); a00h = ffma2(w0h, a0h, a00h);
        a01l = ffma2(w0l, a1l, a01l); a01h = ffma2(w0h, a1h, a01h);
        a10l = ffma2(w1l, a0l, a10l); a10h = ffma2(w1h, a0h, a10h);
        a11l = ffma2(w1l, a1l, a11l); a11h = ffma2(w1h, a1h, a11h);
    }
    P[(kq*2 + 0)*256 + r0      ] = (a00l.x + a00l.y) + (a00h.x + a00h.y);
    P[(kq*2 + 1)*256 + r0      ] = (a01l.x + a01l.y) + (a01h.x + a01h.y);
    P[(kq*2 + 0)*256 + r0 + 128] = (a10l.x + a10l.y) + (a10h.x + a10h.y);
    P[(kq*2 + 1)*256 + r0 + 128] = (a11l.x + a11l.y) + (a11h.x + a11h.y);
}

// ---------------- main kernel ----------------
__global__ void __launch_bounds__(NTHR, 1)
ncde_stream(const float* __restrict__ coeffs, const float* __restrict__ times_g,
            const float* __restrict__ W_init, const float* __restrict__ b_init,
            const float* __restrict__ b_in,   const float* __restrict__ b_hh,
            const float* __restrict__ b_out,  const float* __restrict__ bc1,
            const float* __restrict__ Wc2,    const float* __restrict__ bc2,
            float* __restrict__ out) {
    __shared__ float sT[LT];
    __shared__ float sB[5*HD];          // b_in | b_h0 | b_h1 | b_out | bc1
    __shared__ float Z [COLS*AST];      // [c][260]: rows 0..255, x at 256..258, 0 at 259
    __shared__ float A0[COLS*AST];
    __shared__ float A1[COLS*AST];
    __shared__ float P [16*256];        // [kq*2+col][row] partials = 16 KB

    const int tid = threadIdx.x;
    const int rp  = tid & 127;          // row-pair (rows rp, rp+128)
    const int kq  = tid >> 7;           // K-eighth 0..7
    const int gb  = blockIdx.x * COLS;

    if (tid < LT) sT[tid] = times_g[tid];
    {
        const float* bs[5] = {b_in, b_hh, b_hh + HD, b_out, bc1};
        for (int i = tid; i < 5*HD; i += NTHR) sB[i] = bs[i >> 8][i & 255];
    }
    __syncthreads();

    const float tstart = sT[0];
    const float dt = (sT[LT-1] - tstart) / (float)NSTEPS;
    float t = tstart;

    auto write_x = [&](int col, float tt) {
        int idx = 0;
#pragma unroll
        for (int i = 1; i <= LT-2; i++) idx = (sT[i] <= tt) ? i : idx;
        float ta = sT[idx], tb = sT[idx+1];
        float w = (tt - ta) / (tb - ta), om = 1.0f - w;
        const float* c0 = coeffs + ((gb + col)*LT + idx)*DIM;
        float* xs = &Z[col*AST + 256];
        xs[0] = c0[0]*om + c0[DIM+0]*w;
        xs[1] = c0[1]*om + c0[DIM+1]*w;
        xs[2] = c0[2]*om + c0[DIM+2]*w;
        xs[3] = 0.0f;
    };

    // ---- init: x(t0), then z0 = W_init @ x + b_init ----
    if (tid < COLS) write_x(tid, t);
    __syncthreads();
    if (tid < HD) {
        int row = tid;
        float wa = __ldg(W_init + row*DIM+0), wb = __ldg(W_init + row*DIM+1),
              wc = __ldg(W_init + row*DIM+2), bb = __ldg(b_init + row);
#pragma unroll
        for (int c = 0; c < COLS; c++) {
            const float* xs = &Z[c*AST + 256];
            Z[c*AST + row] = bb + wa*xs[0] + wb*xs[1] + wc*xs[2];
        }
    }
    __syncthreads();

    const float4* wpIN  = g_wpack + OFFP_IN;
    const float4* wpH0  = g_wpack + OFFP_H0;
    const float4* wpH1  = g_wpack + OFFP_H1;
    const float4* wpOUT = g_wpack + OFFP_OUT;
    // 8-way K bounds: L1 (65 blocks: 9+7*8), hidden (64 blocks: 8 each)
    const int b65lo = (kq == 0) ? 0 : 9 + (kq-1)*8;
    const int b65hi = 9 + kq*8;
    const int b64lo = kq << 3, b64hi = (kq+1) << 3;

    // finalize: 512 threads, each (row, col): sum 8 partials, apply FXPR, write DST
#define FINALIZE(DST, BIASARR, FXPR)                                          \
    if (tid < 512) {                                                          \
        int row = tid & 255, col = tid >> 8;                                  \
        float acc = P[(0*2 + col)*256 + row];                                 \
        _Pragma("unroll")                                                     \
        for (int q = 1; q < 8; q++) acc += P[(q*2 + col)*256 + row];          \
        float pv = acc + BIASARR[row];                                        \
        DST[col*AST + row] = FXPR;                                            \
    }

    // ---- main Euler loop: 8 __syncthreads per step ----
    for (int s = 0; s < NSTEPS; s++) {
        // L1: lipswish(W_in @ [z;x] + b_in) -> A0
        pdot(wpIN, Z, b65lo, b65hi, rp, kq, P);
        __syncthreads();
        FINALIZE(A0, (sB + 0*HD), lipswish(pv))
        __syncthreads();
        // L2: -> A1
        pdot(wpH0, A0, b64lo, b64hi, rp, kq, P);
        __syncthreads();
        FINALIZE(A1, (sB + 1*HD), lipswish(pv))
        __syncthreads();
        // L3: -> A0
        pdot(wpH1, A1, b64lo, b64hi, rp, kq, P);
        __syncthreads();
        FINALIZE(A0, (sB + 2*HD), lipswish(pv))
        __syncthreads();
        // L4: z += dt*tanh(.); x(t+dt) by threads 512..513 in parallel
        pdot(wpOUT, A0, b64lo, b64hi, rp, kq, P);
        __syncthreads();
        t += dt;
        if (tid < 512) {
            int row = tid & 255, col = tid >> 8;
            float acc = P[(0*2 + col)*256 + row];
#pragma unroll
            for (int q = 1; q < 8; q++) acc += P[(q*2 + col)*256 + row];
            float f = tanhf(acc + sB[3*HD + row]);
            Z[col*AST + row] = fmaf(dt, f, Z[col*AST + row]);
        } else if (tid < 512 + COLS) {
            write_x(tid - 512, t);
        }
        __syncthreads();
    }

    // ---- classifier hidden: relu(Wc1 @ z + bc1) -> A0 ----
    pdot(g_wpack + OFFP_C1, Z, b64lo, b64hi, rp, kq, P);
    __syncthreads();
    FINALIZE(A0, (sB + 4*HD), fmaxf(pv, 0.0f))
    __syncthreads();

    // ---- out = Wc2 @ h + bc2 : 20 dots per CTA ----
    if (tid < COLS * NCLASS) {
        int c = tid / NCLASS, cls = tid % NCLASS;
        const float4* wr = (const float4*)(Wc2 + cls * HD);
        const float* hb = &A0[c*AST];
        float2 se = {0,0}, so = {0,0};
#pragma unroll 8
        for (int k4 = 0; k4 < 64; k4++) {
            float4 w = __ldg(wr + k4);
            float4 h = *(const float4*)(hb + (k4 << 2));
            se = ffma2(make_float2(w.x, w.y), make_float2(h.x, h.y), se);
            so = ffma2(make_float2(w.z, w.w), make_float2(h.z, h.w), so);
        }
        out[(gb + c) * NCLASS + cls] = __ldg(bc2 + cls) + (se.x + se.y) + (so.x + so.y);
    }
#undef FINALIZE
}

// ---------------- launch ----------------
extern "C" void kernel_launch(void* const* d_in, const int* in_sizes, int n_in,
                              void* d_out, int out_size) {
    (void)in_sizes; (void)n_in; (void)out_size;
    const float* coeffs = (const float*)d_in[0];
    const float* times  = (const float*)d_in[1];
    const float* W_init = (const float*)d_in[2];
    const float* b_init = (const float*)d_in[3];
    const float* W_in   = (const float*)d_in[4];
    const float* b_in   = (const float*)d_in[5];
    const float* W_hh   = (const float*)d_in[6];
    const float* b_hh   = (const float*)d_in[7];
    const float* W_out  = (const float*)d_in[8];
    const float* b_out  = (const float*)d_in[9];
    const float* Wc1    = (const float*)d_in[10];
    const float* bc1    = (const float*)d_in[11];
    const float* Wc2    = (const float*)d_in[12];
    const float* bc2    = (const float*)d_in[13];

    repack_kernel<<<321, 256>>>(W_in, W_hh, W_out, Wc1);
    ncde_stream<<<NCTA, NTHR>>>(coeffs, times, W_init, b_init,
                                b_in, b_hh, b_out, bc1, Wc2, bc2,
                                (float*)d_out);
}